// round 5
// baseline (speedup 1.0000x reference)
#include <cuda_runtime.h>
#include <math.h>
#include <stdint.h>

#define T_TOK 2048
#define DIM   2048
#define NEXP  8
#define EW    (NEXP * DIM * DIM)   // expert weight elems (33.5M)
#define SW    (DIM * DIM)          // shared weight / activation elems

// ---------------- scratch (device globals) ----------------------------------
__device__ float    g_G [T_TOK * DIM];
__device__ float    g_U [T_TOK * DIM];
// bf16 hi/lo split operands
__device__ uint16_t g_gw_h[EW], g_gw_l[EW];
__device__ uint16_t g_uw_h[EW], g_uw_l[EW];
__device__ uint16_t g_dw_h[EW], g_dw_l[EW];
__device__ uint16_t g_sg_h[SW], g_sg_l[SW];
__device__ uint16_t g_su_h[SW], g_su_l[SW];
__device__ uint16_t g_sd_h[SW], g_sd_l[SW];
__device__ uint16_t g_x_h [SW], g_x_l [SW];   // raw x split
__device__ uint16_t g_xs_h[SW], g_xs_l[SW];   // x*score split
__device__ uint16_t g_H_h [SW], g_H_l [SW];   // swiglu output split
__device__ int g_counts[NEXP], g_cursor[NEXP], g_off[NEXP + 1];
__device__ int g_eidx[T_TOK], g_perm[T_TOK];
__device__ int g_tile_e[32], g_tile_m[32], g_ntiles;

// ---------------- helpers ----------------------------------------------------
__device__ __forceinline__ uint32_t smem_u32(const void* p) {
  uint32_t a;
  asm("{ .reg .u64 t; cvta.to.shared.u64 t, %1; cvt.u32.u64 %0, t; }" : "=r"(a) : "l"(p));
  return a;
}
__device__ __forceinline__ void cp16(uint32_t dst, const void* src) {
  asm volatile("cp.async.cg.shared.global [%0], [%1], 16;" :: "r"(dst), "l"(src));
}
__device__ __forceinline__ uint32_t pack_hi(float x, float y) {
  return __byte_perm(__float_as_uint(x), __float_as_uint(y), 0x7632);
}
__device__ __forceinline__ uint32_t pack_lo(float x, float y) {
  float lx = x - __uint_as_float(__float_as_uint(x) & 0xFFFF0000u);
  float ly = y - __uint_as_float(__float_as_uint(y) & 0xFFFF0000u);
  uint32_t r;
  asm("cvt.rn.bf16x2.f32 %0, %1, %2;" : "=r"(r) : "f"(ly), "f"(lx));
  return r;
}
__device__ __forceinline__ void mma16816(float* d, const uint32_t* a,
                                         uint32_t b0, uint32_t b1) {
  asm volatile("mma.sync.aligned.m16n8k16.row.col.f32.bf16.bf16.f32 "
               "{%0,%1,%2,%3}, {%4,%5,%6,%7}, {%8,%9}, {%0,%1,%2,%3};"
               : "+f"(d[0]), "+f"(d[1]), "+f"(d[2]), "+f"(d[3])
               : "r"(a[0]), "r"(a[1]), "r"(a[2]), "r"(a[3]), "r"(b0), "r"(b1));
}
#define LDSM4(r, a)                                                            \
  asm volatile("ldmatrix.sync.aligned.m8n8.x4.shared.b16 {%0,%1,%2,%3}, [%4];" \
    : "=r"((r)[0]), "=r"((r)[1]), "=r"((r)[2]), "=r"((r)[3]) : "r"(a))
#define LDSM4T(r, a)                                                           \
  asm volatile("ldmatrix.sync.aligned.m8n8.x4.trans.shared.b16 {%0,%1,%2,%3}, [%4];" \
    : "=r"((r)[0]), "=r"((r)[1]), "=r"((r)[2]), "=r"((r)[3]) : "r"(a))

// ---------------- split kernel (fp32 -> bf16 hi + lo) ------------------------
__global__ void split_kernel(const float4* __restrict__ src,
                             uint2* __restrict__ hi, uint2* __restrict__ lo,
                             int n4) {
  int i = blockIdx.x * blockDim.x + threadIdx.x;
  if (i >= n4) return;
  float4 v = src[i];
  uint2 h, l;
  h.x = pack_hi(v.x, v.y); h.y = pack_hi(v.z, v.w);
  l.x = pack_lo(v.x, v.y); l.y = pack_lo(v.z, v.w);
  hi[i] = h; lo[i] = l;
}

// ---------------- tiny setup kernels ----------------------------------------
__global__ void init_kernel() {
  int t = threadIdx.x;
  if (t < NEXP) { g_counts[t] = 0; g_cursor[t] = 0; }
}

__global__ void router_kernel(const float* __restrict__ x,
                              const float* __restrict__ rw) {
  int tok  = (blockIdx.x * blockDim.x + threadIdx.x) >> 5;
  int lane = threadIdx.x & 31;
  if (tok >= T_TOK) return;
  const float* xr = x + (size_t)tok * DIM;
  float acc[NEXP];
#pragma unroll
  for (int e = 0; e < NEXP; e++) acc[e] = 0.f;
  for (int k = lane; k < DIM; k += 32) {
    float xv = xr[k];
    const float4* w4 = reinterpret_cast<const float4*>(rw + (size_t)k * NEXP);
    float4 w0 = w4[0], w1 = w4[1];
    acc[0] = fmaf(xv, w0.x, acc[0]); acc[1] = fmaf(xv, w0.y, acc[1]);
    acc[2] = fmaf(xv, w0.z, acc[2]); acc[3] = fmaf(xv, w0.w, acc[3]);
    acc[4] = fmaf(xv, w1.x, acc[4]); acc[5] = fmaf(xv, w1.y, acc[5]);
    acc[6] = fmaf(xv, w1.z, acc[6]); acc[7] = fmaf(xv, w1.w, acc[7]);
  }
#pragma unroll
  for (int o = 16; o > 0; o >>= 1)
#pragma unroll
    for (int e = 0; e < NEXP; e++)
      acc[e] += __shfl_down_sync(0xffffffffu, acc[e], o);
  float sc = 0.f;
  if (lane == 0) {
    float mx = acc[0]; int im = 0;
#pragma unroll
    for (int e = 1; e < NEXP; e++) if (acc[e] > mx) { mx = acc[e]; im = e; }
    sc = 1.f / (1.f + expf(-mx));
    g_eidx[tok] = im;
    atomicAdd(&g_counts[im], 1);
  }
  sc = __shfl_sync(0xffffffffu, sc, 0);
  const float4* x4 = reinterpret_cast<const float4*>(xr);
  uint2* xh = reinterpret_cast<uint2*>(g_x_h)  + (size_t)tok * (DIM / 4);
  uint2* xl = reinterpret_cast<uint2*>(g_x_l)  + (size_t)tok * (DIM / 4);
  uint2* sh = reinterpret_cast<uint2*>(g_xs_h) + (size_t)tok * (DIM / 4);
  uint2* sl = reinterpret_cast<uint2*>(g_xs_l) + (size_t)tok * (DIM / 4);
  for (int k = lane; k < DIM / 4; k += 32) {
    float4 v = x4[k];
    uint2 h, l;
    h.x = pack_hi(v.x, v.y); h.y = pack_hi(v.z, v.w);
    l.x = pack_lo(v.x, v.y); l.y = pack_lo(v.z, v.w);
    xh[k] = h; xl[k] = l;
    float4 s = make_float4(v.x * sc, v.y * sc, v.z * sc, v.w * sc);
    h.x = pack_hi(s.x, s.y); h.y = pack_hi(s.z, s.w);
    l.x = pack_lo(s.x, s.y); l.y = pack_lo(s.z, s.w);
    sh[k] = h; sl[k] = l;
  }
}

__global__ void offsets_kernel() {
  int o = 0, nt = 0;
  for (int e = 0; e < NEXP; e++) {
    g_off[e] = o;
    int c = g_counts[e];
    for (int m = 0; m < c; m += 128) { g_tile_e[nt] = e; g_tile_m[nt] = o + m; nt++; }
    o += c;
  }
  g_off[NEXP] = o;
  g_ntiles = nt;
}

__global__ void scatter_kernel() {
  int t = blockIdx.x * blockDim.x + threadIdx.x;
  if (t >= T_TOK) return;
  int e = g_eidx[t];
  int p = g_off[e] + atomicAdd(&g_cursor[e], 1);
  g_perm[p] = t;
}

__global__ void swiglu_kernel() {
  int i = blockIdx.x * blockDim.x + threadIdx.x;
  if (i >= T_TOK * DIM / 4) return;
  const float4* G4 = reinterpret_cast<const float4*>(g_G);
  const float4* U4 = reinterpret_cast<const float4*>(g_U);
  float4 g = G4[i], u = U4[i], h;
  h.x = g.x / (1.f + expf(-g.x)) * u.x;
  h.y = g.y / (1.f + expf(-g.y)) * u.y;
  h.z = g.z / (1.f + expf(-g.z)) * u.z;
  h.w = g.w / (1.f + expf(-g.w)) * u.w;
  uint2 hh, hl;
  hh.x = pack_hi(h.x, h.y); hh.y = pack_hi(h.z, h.w);
  hl.x = pack_lo(h.x, h.y); hl.y = pack_lo(h.z, h.w);
  reinterpret_cast<uint2*>(g_H_h)[i] = hh;
  reinterpret_cast<uint2*>(g_H_l)[i] = hl;
}

// ---------------- HMMA bf16x3 GEMM core (pre-split operands) ------------------
// C[128,128] tile, K=2048, BK=64, 3-stage cp.async of bf16 hi/lo tiles.
// SMEM stage: Ah[128][72] Al | Bh[64][136] Bl bf16  = 71680 B; x3 = 215040 B.
#define LDA 72
#define LDB 136
#define AH_OFF 0
#define AL_OFF 18432
#define BH_OFF 36864
#define BL_OFF 54272
#define STG_B  71680
#define NCHUNK (DIM / 64)

template<int GA, int SC, int ACCF>
__device__ __forceinline__ void gemm_core(
    const uint16_t* __restrict__ Ah, const uint16_t* __restrict__ Al,
    const uint16_t* __restrict__ Bh, const uint16_t* __restrict__ Bl,
    float* __restrict__ C, int m0, int mEnd, int n0,
    const int* __restrict__ perm) {
  extern __shared__ char sm[];
  const uint32_t smu = smem_u32(sm);
  const int t = threadIdx.x;
  const int lane = t & 31;
  const int wid  = t >> 5;
  const int wm = wid >> 1;            // 0..3
  const int wn = wid & 1;             // 0..1
  const int rsel = lane & 15;         // ldmatrix row select
  const int csel = lane >> 4;         // ldmatrix col-half select

  // fill mappings
  const int am   = t >> 1;            // A row 0..127
  const int ahalf= t & 1;             // which 64B half of 128B row
  const int ga   = m0 + am;
  const bool av  = ga < mEnd;
  const int arow = GA ? (av ? perm[ga] : 0) : (av ? ga : 0);
  const uint16_t* aRowH = Ah + (size_t)arow * DIM + ahalf * 32;
  const uint16_t* aRowL = Al + (size_t)arow * DIM + ahalf * 32;
  const int bkr = t >> 2;             // B k-row 0..63
  const int bq  = t & 3;              // quarter of 256B row
  const uint16_t* bRowH = Bh + (size_t)bkr * DIM + n0 + bq * 32;
  const uint16_t* bRowL = Bl + (size_t)bkr * DIM + n0 + bq * 32;
  const uint32_t dstA = smu + (uint32_t)(am * (LDA * 2) + ahalf * 64);
  const uint32_t dstB = smu + (uint32_t)(bkr * (LDB * 2) + bq * 64);

  float acc[2][8][4];
#pragma unroll
  for (int i = 0; i < 2; i++)
#pragma unroll
    for (int j = 0; j < 8; j++)
#pragma unroll
      for (int q = 0; q < 4; q++) acc[i][j][q] = 0.f;

  auto fill = [&](int st, int c) {
    const int k0 = c * 64;
    const uint32_t sb = (uint32_t)st * STG_B;
#pragma unroll
    for (int i = 0; i < 4; i++) {
      cp16(dstA + sb + AH_OFF + i * 16u, aRowH + k0 + i * 8);
      cp16(dstA + sb + AL_OFF + i * 16u, aRowL + k0 + i * 8);
    }
#pragma unroll
    for (int i = 0; i < 4; i++) {
      cp16(dstB + sb + BH_OFF + i * 16u, bRowH + (size_t)k0 * DIM + i * 8);
      cp16(dstB + sb + BL_OFF + i * 16u, bRowL + (size_t)k0 * DIM + i * 8);
    }
  };

  fill(0, 0);
  asm volatile("cp.async.commit_group;" ::: "memory");
  fill(1, 1);
  asm volatile("cp.async.commit_group;" ::: "memory");

  for (int c = 0; c < NCHUNK; c++) {
    asm volatile("cp.async.wait_group 1;" ::: "memory");
    __syncthreads();
    if (c + 2 < NCHUNK) fill((c + 2) % 3, c + 2);
    asm volatile("cp.async.commit_group;" ::: "memory");

    const uint32_t stg = smu + (uint32_t)((c % 3) * STG_B);
#pragma unroll
    for (int ks = 0; ks < 4; ks++) {
      uint32_t ah[2][4], al[2][4];
#pragma unroll
      for (int mt = 0; mt < 2; mt++) {
        uint32_t ra = stg + (uint32_t)((wm * 32 + mt * 16 + rsel) * (LDA * 2) +
                                       (ks * 16 + csel * 8) * 2);
        LDSM4(ah[mt], ra + AH_OFF);
        LDSM4(al[mt], ra + AL_OFF);
      }
#pragma unroll
      for (int np = 0; np < 4; np++) {
        uint32_t rb = stg + (uint32_t)((ks * 16 + rsel) * (LDB * 2) +
                                       (wn * 64 + np * 16 + csel * 8) * 2);
        uint32_t bh[4], bl[4];
        LDSM4T(bh, rb + BH_OFF);
        LDSM4T(bl, rb + BL_OFF);
#pragma unroll
        for (int mt = 0; mt < 2; mt++) {
          mma16816(acc[mt][np * 2],     ah[mt], bh[0], bh[1]);
          mma16816(acc[mt][np * 2],     ah[mt], bl[0], bl[1]);
          mma16816(acc[mt][np * 2],     al[mt], bh[0], bh[1]);
          mma16816(acc[mt][np * 2 + 1], ah[mt], bh[2], bh[3]);
          mma16816(acc[mt][np * 2 + 1], ah[mt], bl[2], bl[3]);
          mma16816(acc[mt][np * 2 + 1], al[mt], bh[2], bh[3]);
        }
      }
    }
    __syncthreads();
  }

  // ---- epilogue ------------------------------------------------------------
#pragma unroll
  for (int mt = 0; mt < 2; mt++) {
    const int rb = m0 + wm * 32 + mt * 16 + (lane >> 2);
#pragma unroll
    for (int h = 0; h < 2; h++) {
      const int row = rb + h * 8;
      if (row >= mEnd) continue;
      const int crow = SC ? perm[row] : row;
      float* cp = C + (size_t)crow * DIM + n0 + wn * 64 + (lane & 3) * 2;
#pragma unroll
      for (int nf = 0; nf < 8; nf++) {
        float2 v = make_float2(acc[mt][nf][h * 2], acc[mt][nf][h * 2 + 1]);
        float* dst = cp + nf * 8;
        if (ACCF) {
          float2 o = *reinterpret_cast<const float2*>(dst);
          v.x += o.x; v.y += o.y;
        }
        *reinterpret_cast<float2*>(dst) = v;
      }
    }
  }
}

template<int ACCF>
__global__ void __launch_bounds__(256, 1)
gemm_dense_kernel(const uint16_t* __restrict__ Ah, const uint16_t* __restrict__ Al,
                  const uint16_t* __restrict__ Bh, const uint16_t* __restrict__ Bl,
                  float* __restrict__ C) {
  gemm_core<0, 0, ACCF>(Ah, Al, Bh, Bl, C, blockIdx.y * 128, T_TOK,
                        blockIdx.x * 128, nullptr);
}

template<int GA, int SC, int ACCF>
__global__ void __launch_bounds__(256, 1)
gemm_grouped_kernel(const uint16_t* __restrict__ Ah, const uint16_t* __restrict__ Al,
                    const uint16_t* __restrict__ Wh, const uint16_t* __restrict__ Wl,
                    float* __restrict__ C) {
  int ti = blockIdx.y;
  if (ti >= g_ntiles) return;
  int e = g_tile_e[ti];
  gemm_core<GA, SC, ACCF>(Ah, Al, Wh + (size_t)e * DIM * DIM,
                          Wl + (size_t)e * DIM * DIM, C,
                          g_tile_m[ti], g_off[e + 1], blockIdx.x * 128, g_perm);
}

// ---------------- launch -----------------------------------------------------
extern "C" void kernel_launch(void* const* d_in, const int* in_sizes, int n_in,
                              void* d_out, int out_size) {
  const float* x  = (const float*)d_in[0];
  const float* rw = (const float*)d_in[1];
  const float* gw = (const float*)d_in[2];
  const float* uw = (const float*)d_in[3];
  const float* dw = (const float*)d_in[4];
  const float* sg = (const float*)d_in[5];
  const float* su = (const float*)d_in[6];
  const float* sd = (const float*)d_in[7];
  float* out = (float*)d_out;

  float *pG, *pU;
  uint16_t *gwh, *gwl, *uwh, *uwl, *dwh, *dwl;
  uint16_t *sgh, *sgl, *suh, *sul, *sdh, *sdl;
  uint16_t *xh, *xl, *xsh, *xsl, *Hh, *Hl;
  cudaGetSymbolAddress((void**)&pG,  g_G);
  cudaGetSymbolAddress((void**)&pU,  g_U);
  cudaGetSymbolAddress((void**)&gwh, g_gw_h); cudaGetSymbolAddress((void**)&gwl, g_gw_l);
  cudaGetSymbolAddress((void**)&uwh, g_uw_h); cudaGetSymbolAddress((void**)&uwl, g_uw_l);
  cudaGetSymbolAddress((void**)&dwh, g_dw_h); cudaGetSymbolAddress((void**)&dwl, g_dw_l);
  cudaGetSymbolAddress((void**)&sgh, g_sg_h); cudaGetSymbolAddress((void**)&sgl, g_sg_l);
  cudaGetSymbolAddress((void**)&suh, g_su_h); cudaGetSymbolAddress((void**)&sul, g_su_l);
  cudaGetSymbolAddress((void**)&sdh, g_sd_h); cudaGetSymbolAddress((void**)&sdl, g_sd_l);
  cudaGetSymbolAddress((void**)&xh,  g_x_h);  cudaGetSymbolAddress((void**)&xl,  g_x_l);
  cudaGetSymbolAddress((void**)&xsh, g_xs_h); cudaGetSymbolAddress((void**)&xsl, g_xs_l);
  cudaGetSymbolAddress((void**)&Hh,  g_H_h);  cudaGetSymbolAddress((void**)&Hl,  g_H_l);

  const int smem_b = 3 * STG_B;
  cudaFuncSetAttribute(gemm_dense_kernel<0>,
                       cudaFuncAttributeMaxDynamicSharedMemorySize, smem_b);
  cudaFuncSetAttribute(gemm_grouped_kernel<1, 0, 0>,
                       cudaFuncAttributeMaxDynamicSharedMemorySize, smem_b);
  cudaFuncSetAttribute(gemm_grouped_kernel<0, 1, 1>,
                       cudaFuncAttributeMaxDynamicSharedMemorySize, smem_b);

  // routing + activation split
  init_kernel<<<1, 32>>>();
  router_kernel<<<T_TOK / 8, 256>>>(x, rw);
  offsets_kernel<<<1, 1>>>();
  scatter_kernel<<<T_TOK / 256, 256>>>();

  // weight splits (bandwidth-bound, ~125us total)
  const int ew4 = EW / 4, sw4 = SW / 4;
  split_kernel<<<(ew4 + 255) / 256, 256>>>((const float4*)gw, (uint2*)gwh, (uint2*)gwl, ew4);
  split_kernel<<<(ew4 + 255) / 256, 256>>>((const float4*)uw, (uint2*)uwh, (uint2*)uwl, ew4);
  split_kernel<<<(ew4 + 255) / 256, 256>>>((const float4*)dw, (uint2*)dwh, (uint2*)dwl, ew4);
  split_kernel<<<(sw4 + 255) / 256, 256>>>((const float4*)sg, (uint2*)sgh, (uint2*)sgl, sw4);
  split_kernel<<<(sw4 + 255) / 256, 256>>>((const float4*)su, (uint2*)suh, (uint2*)sul, sw4);
  split_kernel<<<(sw4 + 255) / 256, 256>>>((const float4*)sd, (uint2*)sdh, (uint2*)sdl, sw4);

  const int swi_blocks = (T_TOK * DIM / 4 + 255) / 256;
  dim3 gden(DIM / 128, T_TOK / 128);   // (16, 16)
  dim3 ggrp(DIM / 128, 24);

  // shared expert
  gemm_dense_kernel<0><<<gden, 256, smem_b>>>(xh, xl, sgh, sgl, pG);
  gemm_dense_kernel<0><<<gden, 256, smem_b>>>(xh, xl, suh, sul, pU);
  swiglu_kernel<<<swi_blocks, 256>>>();
  gemm_dense_kernel<0><<<gden, 256, smem_b>>>(Hh, Hl, sdh, sdl, out);

  // routed experts
  gemm_grouped_kernel<1, 0, 0><<<ggrp, 256, smem_b>>>(xsh, xsl, gwh, gwl, pG);
  gemm_grouped_kernel<1, 0, 0><<<ggrp, 256, smem_b>>>(xsh, xsl, uwh, uwl, pU);
  swiglu_kernel<<<swi_blocks, 256>>>();
  gemm_grouped_kernel<0, 1, 1><<<ggrp, 256, smem_b>>>(Hh, Hl, dwh, dwl, out);
}